// round 9
// baseline (speedup 1.0000x reference)
#include <cuda_runtime.h>

#define BB 16
#define NN 8192
#define SS 1024
#define GG 32
#define CC 64
#define OC 128
#define FULL 0xffffffffu

// ---------------- scratch (device globals; no runtime allocation) ----------------
__device__ float4 g_pts[BB * NN];                 // xyz + |p|^2
__device__ int    g_fps[BB * SS];                 // fps indices
__device__ float  g_F[(size_t)BB * NN * OC];      // per-point feature @ Wf (64 MB)

// ---------------- packed f32x2 helpers (bit-identical .rn rounding) ----------------
__device__ __forceinline__ unsigned long long f2pack(float a, float b) {
    unsigned long long r;
    asm("mov.b64 %0, {%1, %2};" : "=l"(r) : "f"(a), "f"(b));
    return r;
}
__device__ __forceinline__ void f2unpack(unsigned long long v, float& a, float& b) {
    asm("mov.b64 {%0, %1}, %2;" : "=f"(a), "=f"(b) : "l"(v));
}
__device__ __forceinline__ unsigned long long fadd2(unsigned long long a, unsigned long long b) {
    unsigned long long r;
    asm("add.rn.f32x2 %0, %1, %2;" : "=l"(r) : "l"(a), "l"(b));
    return r;
}
__device__ __forceinline__ unsigned long long fmul2(unsigned long long a, unsigned long long b) {
    unsigned long long r;
    asm("mul.rn.f32x2 %0, %1, %2;" : "=l"(r) : "l"(a), "l"(b));
    return r;
}

// ---------------- K0: pack coords as float4 with squared norm ----------------
__global__ void k_prep(const float* __restrict__ coor) {
    int p = blockIdx.x * 256 + threadIdx.x;
    int b = blockIdx.y;
    if (p < NN) {
        float x = coor[((size_t)b * 3 + 0) * NN + p];
        float y = coor[((size_t)b * 3 + 1) * NN + p];
        float z = coor[((size_t)b * 3 + 2) * NN + p];
        g_pts[b * NN + p] = make_float4(x, y, z, x * x + y * y + z * z);
    }
}

// ---------------- K1: farthest point sampling (verified R2 version) ----------------
__global__ __launch_bounds__(1024) void k_fps(float* __restrict__ outc) {
    __shared__ unsigned long long s_red[2][32];
    int b = blockIdx.x, tid = threadIdx.x, lane = tid & 31, wid = tid >> 5;
    const float4* pts = &g_pts[b * NN];

    unsigned long long px2[4], py2[4], pz2[4];
    float dist[8];
#pragma unroll
    for (int k = 0; k < 4; k++) {
        float4 a = pts[tid + ((2 * k) << 10)];
        float4 c = pts[tid + ((2 * k + 1) << 10)];
        px2[k] = f2pack(a.x, c.x);
        py2[k] = f2pack(a.y, c.y);
        pz2[k] = f2pack(a.z, c.z);
        dist[2 * k] = 1e10f; dist[2 * k + 1] = 1e10f;
    }
    float4 c0 = pts[0];
    float cx = c0.x, cy = c0.y, cz = c0.z;
    int cur = 0;

    for (int s = 0; s < SS; s++) {
        if (tid == 0) {
            g_fps[b * SS + s] = cur;
            outc[((size_t)b * 3 + 0) * SS + s] = cx;
            outc[((size_t)b * 3 + 1) * SS + s] = cy;
            outc[((size_t)b * 3 + 2) * SS + s] = cz;
        }
        unsigned long long ncx2 = f2pack(-cx, -cx);
        unsigned long long ncy2 = f2pack(-cy, -cy);
        unsigned long long ncz2 = f2pack(-cz, -cz);
        float bm = -1.0f;
#pragma unroll
        for (int k = 0; k < 4; k++) {
            unsigned long long dx2 = fadd2(px2[k], ncx2);
            unsigned long long dy2 = fadd2(py2[k], ncy2);
            unsigned long long dz2 = fadd2(pz2[k], ncz2);
            unsigned long long sq = fadd2(fadd2(fmul2(dx2, dx2), fmul2(dy2, dy2)),
                                          fmul2(dz2, dz2));
            float d0, d1;
            f2unpack(sq, d0, d1);
            dist[2 * k]     = fminf(dist[2 * k], d0);
            dist[2 * k + 1] = fminf(dist[2 * k + 1], d1);
            bm = fmaxf(bm, dist[2 * k]);
            bm = fmaxf(bm, dist[2 * k + 1]);
        }
        int bk = 7;
#pragma unroll
        for (int k = 6; k >= 0; k--) bk = (dist[k] == bm) ? k : bk;

        unsigned vb = __float_as_uint(bm);
        unsigned m  = __reduce_max_sync(FULL, vb);
        unsigned rk = (vb == m) ? (unsigned)(NN - 1 - (tid + (bk << 10))) : 0u;
        unsigned m2 = __reduce_max_sync(FULL, rk);   // max(N-1-i) == min i
        if (lane == 0)
            s_red[s & 1][wid] = ((unsigned long long)m << 32) | m2;
        __syncthreads();
        unsigned long long v = s_red[s & 1][lane];
        unsigned hi = (unsigned)(v >> 32);
        unsigned M  = __reduce_max_sync(FULL, hi);
        unsigned lo = (hi == M) ? (unsigned)v : 0u;
        unsigned M2 = __reduce_max_sync(FULL, lo);
        int nf = NN - 1 - (int)M2;
        float4 cc = pts[nf];
        cx = cc.x; cy = cc.y; cz = cc.z; cur = nf;
    }
}

// ---------------- sortable squared-distance key ----------------
__device__ __forceinline__ unsigned long long dist_key(const float4& q, float cx, float cy,
                                                       float cz, float cw, unsigned idx) {
    float dot = fmaf(cx, q.x, fmaf(cy, q.y, cz * q.z));
    float d   = fmaf(-2.f, dot, cw + q.w);
    unsigned bits = __float_as_uint(d);
    unsigned u = bits ^ (unsigned)(((int)bits >> 31) | (int)0x80000000);
    return ((unsigned long long)u << 32) | idx;
}

// ---------------- fallback: exact replace-max scan (verified R2 algorithm) ----------------
__device__ unsigned long long exact_scan(const float4* pts, float cx, float cy,
                                         float cz, float cw, int lane) {
    float4 p = pts[lane];
    unsigned long long kept = dist_key(p, cx, cy, cz, cw, (unsigned)lane);

    unsigned thr_hi; unsigned long long thr_key; int maxLane;
    {
        unsigned hi = (unsigned)(kept >> 32);
        unsigned M  = __reduce_max_sync(FULL, hi);
        unsigned lo = (hi == M) ? (unsigned)kept : 0u;
        unsigned M2 = __reduce_max_sync(FULL, lo);
        thr_hi = M; thr_key = ((unsigned long long)M << 32) | M2;
        maxLane = __ffs(__ballot_sync(FULL, kept == thr_key)) - 1;
    }
    for (int base = 32; base < NN; base += 32) {
        float4 q = pts[base + lane];
        unsigned long long key = dist_key(q, cx, cy, cz, cw, (unsigned)(base + lane));
        unsigned mask = __ballot_sync(FULL, (unsigned)(key >> 32) < thr_hi);
        while (mask) {
            int src = __ffs(mask) - 1; mask &= mask - 1;
            unsigned long long kk = __shfl_sync(FULL, key, src);
            if (kk < thr_key) {
                if (lane == maxLane) kept = kk;
                unsigned hi = (unsigned)(kept >> 32);
                unsigned M  = __reduce_max_sync(FULL, hi);
                unsigned lo = (hi == M) ? (unsigned)kept : 0u;
                unsigned M2 = __reduce_max_sync(FULL, lo);
                thr_hi = M; thr_key = ((unsigned long long)M << 32) | M2;
                maxLane = __ffs(__ballot_sync(FULL, kept == thr_key)) - 1;
            }
        }
    }
    return kept;
}

// ---------------- K2: grouping (per-lane local top-6 + extract-min merge) + fused conv ----------------
__global__ __launch_bounds__(512) void k_group(const float* __restrict__ W,
                                               float* __restrict__ outf) {
    int b    = blockIdx.y;
    int warp = threadIdx.x >> 5, lane = threadIdx.x & 31;
    int s    = blockIdx.x * 16 + warp;
    const float4* pts = &g_pts[b * NN];

    float4 c = pts[g_fps[b * SS + s]];
    float cx = c.x, cy = c.y, cz = c.z, cw = c.w;

    // ---- phase 1: per-lane sorted top-6 over 256 strided points (no warp sync) ----
    const unsigned long long UMX = 0xffffffffffffffffull;
    unsigned long long l0 = UMX, l1 = UMX, l2 = UMX, l3 = UMX, l4 = UMX, l5 = UMX;
#pragma unroll 4
    for (int i = 0; i < NN / 32; i++) {
        unsigned idx = (unsigned)((i << 5) + lane);
        float4 q = pts[idx];
        unsigned long long key = dist_key(q, cx, cy, cz, cw, idx);
        if (key < l5) {
            l5 = key;
            unsigned long long t;
            if (l5 < l4) { t = l4; l4 = l5; l5 = t; }
            if (l4 < l3) { t = l3; l3 = l4; l4 = t; }
            if (l3 < l2) { t = l2; l2 = l3; l3 = t; }
            if (l2 < l1) { t = l1; l1 = l2; l2 = t; }
            if (l1 < l0) { t = l0; l0 = l1; l1 = t; }
        }
    }

    // ---- phase 2: 32 extract-min rounds over the 32 sorted 6-lists ----
    unsigned long long kept = UMX;
    int hp = 0;
#pragma unroll 1
    for (int r = 0; r < GG; r++) {
        unsigned long long head =
            (hp == 0) ? l0 : (hp == 1) ? l1 : (hp == 2) ? l2 :
            (hp == 3) ? l3 : (hp == 4) ? l4 : (hp == 5) ? l5 : UMX;
        unsigned hi = (unsigned)(head >> 32);
        unsigned mh = __reduce_min_sync(FULL, hi);
        unsigned lo = (hi == mh) ? (unsigned)head : 0xffffffffu;
        unsigned ml = __reduce_min_sync(FULL, lo);
        unsigned long long win = ((unsigned long long)mh << 32) | ml;
        if (lane == r) kept = win;
        if (head == win) hp++;
    }
    // exactness guard: a lane that fed all 6 entries into the winners may have
    // discarded a true top-32 member -> exact fallback (P ~ 1%).
    if (__ballot_sync(FULL, hp >= 6))
        kept = exact_scan(pts, cx, cy, cz, cw, lane);

    // ---- ball-query replacement (RADIUS^2 = 1; sortable(1.0f) = 0xBF800000) ----
    unsigned khi = (unsigned)(kept >> 32);
    unsigned Mn  = __reduce_min_sync(FULL, khi);
    unsigned lon = (khi == Mn) ? (unsigned)kept : 0xffffffffu;
    unsigned M2n = __reduce_min_sync(FULL, lon);
    int nidx  = (int)M2n;
    int myidx = (int)(unsigned)kept;
    int outi = (khi > 0xBF800000u) ? nidx : myidx;

    // ---- fused conv + relu + group-max (lane covers channels o4..o4+3) ----
    int o4 = lane * 4;
    float w0[4], w1[4], w2[4];
#pragma unroll
    for (int j = 0; j < 4; j++) {
        w0[j] = __ldg(&W[(o4 + j) * 67 + 64]);
        w1[j] = __ldg(&W[(o4 + j) * 67 + 65]);
        w2[j] = __ldg(&W[(o4 + j) * 67 + 66]);
    }
    float m0 = 0.f, m1 = 0.f, m2 = 0.f, m3 = 0.f;   // relu(v)>=0 => init 0
#pragma unroll 4
    for (int g = 0; g < GG; g++) {
        int ig = __shfl_sync(FULL, outi, g);
        float4 pp = pts[ig];
        float rx = pp.x - cx, ry = pp.y - cy, rz = pp.z - cz;
        const float4 f = *(const float4*)&g_F[((size_t)(b * NN + ig)) * OC + o4];
        float v0 = fmaf(rx, w0[0], f.x); v0 = fmaf(ry, w1[0], v0); v0 = fmaf(rz, w2[0], v0);
        float v1 = fmaf(rx, w0[1], f.y); v1 = fmaf(ry, w1[1], v1); v1 = fmaf(rz, w2[1], v1);
        float v2 = fmaf(rx, w0[2], f.z); v2 = fmaf(ry, w1[2], v2); v2 = fmaf(rz, w2[2], v2);
        float v3 = fmaf(rx, w0[3], f.w); v3 = fmaf(ry, w1[3], v3); v3 = fmaf(rz, w2[3], v3);
        m0 = fmaxf(m0, v0); m1 = fmaxf(m1, v1); m2 = fmaxf(m2, v2); m3 = fmaxf(m3, v3);
    }
    outf[((size_t)(b * OC + o4 + 0)) * SS + s] = m0;
    outf[((size_t)(b * OC + o4 + 1)) * SS + s] = m1;
    outf[((size_t)(b * OC + o4 + 2)) * SS + s] = m2;
    outf[((size_t)(b * OC + o4 + 3)) * SS + s] = m3;
}

// ---------------- K3: dense per-point feature GEMM  F[b][p][o] = fea·Wf ----------------
__global__ __launch_bounds__(256) void k_fgemm(const float* __restrict__ fea,
                                               const float* __restrict__ W) {
    __shared__ float As[32][128];   // [k][p]
    __shared__ float Bs[32][64];    // [k][o]
    int b  = blockIdx.z;
    int p0 = blockIdx.x * 128;
    int o0 = blockIdx.y * 64;
    int tx = threadIdx.x & 15;      // o tile (4 each)
    int ty = threadIdx.x >> 4;      // p tile (8 each)

    float acc[8][4];
#pragma unroll
    for (int i = 0; i < 8; i++)
#pragma unroll
        for (int j = 0; j < 4; j++) acc[i][j] = 0.f;

    for (int kk = 0; kk < CC; kk += 32) {
        __syncthreads();
        for (int i = threadIdx.x; i < 32 * 128; i += 256) {
            int cidx = i >> 7, p = i & 127;
            As[cidx][p] = fea[((size_t)(b * CC + kk + cidx)) * NN + p0 + p];
        }
        for (int i = threadIdx.x; i < 32 * 64; i += 256) {
            int cidx = i >> 6, o = i & 63;
            Bs[cidx][o] = W[(o0 + o) * 67 + kk + cidx];
        }
        __syncthreads();
#pragma unroll
        for (int k = 0; k < 32; k++) {
            float af[8], bf[4];
#pragma unroll
            for (int i = 0; i < 8; i++) af[i] = As[k][ty * 8 + i];
#pragma unroll
            for (int j = 0; j < 4; j++) bf[j] = Bs[k][tx * 4 + j];
#pragma unroll
            for (int i = 0; i < 8; i++)
#pragma unroll
                for (int j = 0; j < 4; j++)
                    acc[i][j] = fmaf(af[i], bf[j], acc[i][j]);
        }
    }
#pragma unroll
    for (int i = 0; i < 8; i++) {
        int p = p0 + ty * 8 + i;
        float4 v = make_float4(acc[i][0], acc[i][1], acc[i][2], acc[i][3]);
        *(float4*)&g_F[((size_t)(b * NN + p)) * OC + o0 + tx * 4] = v;
    }
}

// ---------------- launch: GEMM overlapped with FPS; group (fused final) last ----------------
extern "C" void kernel_launch(void* const* d_in, const int* in_sizes, int n_in,
                              void* d_out, int out_size) {
    const float* coor = (const float*)d_in[0];
    const float* fea  = (const float*)d_in[1];
    const float* W    = (const float*)d_in[2];
    float* outc = (float*)d_out;                 // (B,3,S)
    float* outf = outc + (size_t)BB * 3 * SS;    // (B,2C,S)

    static cudaStream_t s2 = nullptr;
    static cudaEvent_t evA = nullptr, evB = nullptr;
    if (s2 == nullptr) {
        cudaStreamCreateWithFlags(&s2, cudaStreamNonBlocking);
        cudaEventCreateWithFlags(&evA, cudaEventDisableTiming);
        cudaEventCreateWithFlags(&evB, cudaEventDisableTiming);
    }

    // fork: GEMM on side stream (independent of FPS); no cross-kernel spin waits.
    cudaEventRecord(evA, 0);
    cudaStreamWaitEvent(s2, evA, 0);
    k_fgemm<<<dim3(64, 2, BB), 256, 0, s2>>>(fea, W);
    cudaEventRecord(evB, s2);

    k_prep<<<dim3(32, BB), 256>>>(coor);
    k_fps <<<BB, 1024>>>(outc);

    // join: group reads g_F, so wait for GEMM (hidden under FPS)
    cudaStreamWaitEvent(0, evB, 0);
    k_group<<<dim3(64, BB), 512>>>(W, outf);
}

// round 11
// speedup vs baseline: 1.1107x; 1.1107x over previous
#include <cuda_runtime.h>

#define BB 16
#define NN 8192
#define SS 1024
#define GG 32
#define CC 64
#define OC 128
#define FULL 0xffffffffu

// ---------------- scratch (device globals; no runtime allocation) ----------------
__device__ float4 g_pts[BB * NN];                 // xyz + |p|^2
__device__ int    g_fps[BB * SS];                 // fps indices
__device__ float  g_F[(size_t)BB * NN * OC];      // per-point feature @ Wf (64 MB)

// ---------------- packed f32x2 helpers (bit-identical .rn rounding) ----------------
__device__ __forceinline__ unsigned long long f2pack(float a, float b) {
    unsigned long long r;
    asm("mov.b64 %0, {%1, %2};" : "=l"(r) : "f"(a), "f"(b));
    return r;
}
__device__ __forceinline__ void f2unpack(unsigned long long v, float& a, float& b) {
    asm("mov.b64 {%0, %1}, %2;" : "=f"(a), "=f"(b) : "l"(v));
}
__device__ __forceinline__ unsigned long long fadd2(unsigned long long a, unsigned long long b) {
    unsigned long long r;
    asm("add.rn.f32x2 %0, %1, %2;" : "=l"(r) : "l"(a), "l"(b));
    return r;
}
__device__ __forceinline__ unsigned long long fmul2(unsigned long long a, unsigned long long b) {
    unsigned long long r;
    asm("mul.rn.f32x2 %0, %1, %2;" : "=l"(r) : "l"(a), "l"(b));
    return r;
}

// ---------------- K0: pack coords as float4 with squared norm ----------------
__global__ void k_prep(const float* __restrict__ coor) {
    int p = blockIdx.x * 256 + threadIdx.x;
    int b = blockIdx.y;
    if (p < NN) {
        float x = coor[((size_t)b * 3 + 0) * NN + p];
        float y = coor[((size_t)b * 3 + 1) * NN + p];
        float z = coor[((size_t)b * 3 + 2) * NN + p];
        g_pts[b * NN + p] = make_float4(x, y, z, x * x + y * y + z * z);
    }
}

// ---------------- K1: farthest point sampling (verified R2 version) ----------------
__global__ __launch_bounds__(1024) void k_fps(float* __restrict__ outc) {
    __shared__ unsigned long long s_red[2][32];
    int b = blockIdx.x, tid = threadIdx.x, lane = tid & 31, wid = tid >> 5;
    const float4* pts = &g_pts[b * NN];

    unsigned long long px2[4], py2[4], pz2[4];
    float dist[8];
#pragma unroll
    for (int k = 0; k < 4; k++) {
        float4 a = pts[tid + ((2 * k) << 10)];
        float4 c = pts[tid + ((2 * k + 1) << 10)];
        px2[k] = f2pack(a.x, c.x);
        py2[k] = f2pack(a.y, c.y);
        pz2[k] = f2pack(a.z, c.z);
        dist[2 * k] = 1e10f; dist[2 * k + 1] = 1e10f;
    }
    float4 c0 = pts[0];
    float cx = c0.x, cy = c0.y, cz = c0.z;
    int cur = 0;

    for (int s = 0; s < SS; s++) {
        if (tid == 0) {
            g_fps[b * SS + s] = cur;
            outc[((size_t)b * 3 + 0) * SS + s] = cx;
            outc[((size_t)b * 3 + 1) * SS + s] = cy;
            outc[((size_t)b * 3 + 2) * SS + s] = cz;
        }
        unsigned long long ncx2 = f2pack(-cx, -cx);
        unsigned long long ncy2 = f2pack(-cy, -cy);
        unsigned long long ncz2 = f2pack(-cz, -cz);
        float bm = -1.0f;
#pragma unroll
        for (int k = 0; k < 4; k++) {
            unsigned long long dx2 = fadd2(px2[k], ncx2);
            unsigned long long dy2 = fadd2(py2[k], ncy2);
            unsigned long long dz2 = fadd2(pz2[k], ncz2);
            unsigned long long sq = fadd2(fadd2(fmul2(dx2, dx2), fmul2(dy2, dy2)),
                                          fmul2(dz2, dz2));
            float d0, d1;
            f2unpack(sq, d0, d1);
            dist[2 * k]     = fminf(dist[2 * k], d0);
            dist[2 * k + 1] = fminf(dist[2 * k + 1], d1);
            bm = fmaxf(bm, dist[2 * k]);
            bm = fmaxf(bm, dist[2 * k + 1]);
        }
        int bk = 7;
#pragma unroll
        for (int k = 6; k >= 0; k--) bk = (dist[k] == bm) ? k : bk;

        unsigned vb = __float_as_uint(bm);
        unsigned m  = __reduce_max_sync(FULL, vb);
        unsigned rk = (vb == m) ? (unsigned)(NN - 1 - (tid + (bk << 10))) : 0u;
        unsigned m2 = __reduce_max_sync(FULL, rk);   // max(N-1-i) == min i
        if (lane == 0)
            s_red[s & 1][wid] = ((unsigned long long)m << 32) | m2;
        __syncthreads();
        unsigned long long v = s_red[s & 1][lane];
        unsigned hi = (unsigned)(v >> 32);
        unsigned M  = __reduce_max_sync(FULL, hi);
        unsigned lo = (hi == M) ? (unsigned)v : 0u;
        unsigned M2 = __reduce_max_sync(FULL, lo);
        int nf = NN - 1 - (int)M2;
        float4 cc = pts[nf];
        cx = cc.x; cy = cc.y; cz = cc.z; cur = nf;
    }
}

// ---------------- K2: radius-filtered replace-max top-32 + fused conv/relu/max ----------------
// Needed set (max-pool semantics): the min(32, n_inball) nearest points with d<=1,
// plus the nearest (always in-ball since the centroid itself has d~0).
__global__ __launch_bounds__(512) void k_group(const float* __restrict__ W,
                                               float* __restrict__ outf) {
    int b    = blockIdx.y;
    int warp = threadIdx.x >> 5, lane = threadIdx.x & 31;
    int s    = blockIdx.x * 16 + warp;
    const float4* pts = &g_pts[b * NN];

    float4 c = pts[g_fps[b * SS + s]];
    float cx = c.x, cy = c.y, cz = c.z, cw = c.w;

    const unsigned long long UMX    = 0xffffffffffffffffull;
    const unsigned long long RADCAP = 0xBF800001ull << 32;   // admit d <= 1.0 (strict ref: d>1 replaced)

    unsigned long long kept = UMX;         // sentinel = empty slot
    unsigned long long adm  = RADCAP;      // admission threshold = min(cur max kept, RADCAP)
    unsigned adm_hi = 0xBF800001u;
    int maxLane = 0;                       // slot to replace (worst kept / sentinel)

    for (int base = 0; base < NN; base += 32) {
        float4 q = pts[base + lane];
        float dot = fmaf(cx, q.x, fmaf(cy, q.y, cz * q.z));
        float d   = fmaf(-2.f, dot, cw + q.w);
        unsigned bits = __float_as_uint(d);
        unsigned uu = bits ^ (unsigned)(((int)bits >> 31) | (int)0x80000000);
        // prescreen: in-ball AND better than current worst (u32 compare exact:
        // equal-dist candidates arrive later => higher index => can't displace)
        unsigned mask = __ballot_sync(FULL, uu < adm_hi);
        if (mask) {
            unsigned long long key = ((unsigned long long)uu << 32) | (unsigned)(base + lane);
            do {
                int src = __ffs(mask) - 1; mask &= mask - 1;
                unsigned long long kk = __shfl_sync(FULL, key, src);
                if (kk < adm) {
                    if (lane == maxLane) kept = kk;   // replace worst (or fill sentinel)
                    unsigned hi = (unsigned)(kept >> 32);
                    unsigned M  = __reduce_max_sync(FULL, hi);
                    unsigned lo = (hi == M) ? (unsigned)kept : 0u;
                    unsigned M2 = __reduce_max_sync(FULL, lo);
                    unsigned long long true_key = ((unsigned long long)M << 32) | M2;
                    maxLane = __ffs(__ballot_sync(FULL, kept == true_key)) - 1;
                    adm = (true_key < RADCAP) ? true_key : RADCAP;
                    adm_hi = (unsigned)(adm >> 32);
                }
            } while (mask);
        }
    }

    // nearest (min kept; sentinels lose) — fills the replaced/empty slots
    unsigned khi = (unsigned)(kept >> 32);
    unsigned Mn  = __reduce_min_sync(FULL, khi);
    unsigned lon = (khi == Mn) ? (unsigned)kept : 0xffffffffu;
    unsigned M2n = __reduce_min_sync(FULL, lon);
    int nidx  = (int)M2n;
    int myidx = (int)(unsigned)kept;
    int outi = (khi > 0xBF800000u) ? nidx : myidx;   // sentinel/out-of-ball -> nearest

    // ---- fused conv + relu + group-max (lane covers channels o4..o4+3) ----
    int o4 = lane * 4;
    float w0[4], w1[4], w2[4];
#pragma unroll
    for (int j = 0; j < 4; j++) {
        w0[j] = __ldg(&W[(o4 + j) * 67 + 64]);
        w1[j] = __ldg(&W[(o4 + j) * 67 + 65]);
        w2[j] = __ldg(&W[(o4 + j) * 67 + 66]);
    }
    float m0 = 0.f, m1 = 0.f, m2 = 0.f, m3 = 0.f;   // relu(v)>=0 => init 0
#pragma unroll 4
    for (int g = 0; g < GG; g++) {
        int ig = __shfl_sync(FULL, outi, g);
        float4 pp = pts[ig];
        float rx = pp.x - cx, ry = pp.y - cy, rz = pp.z - cz;
        const float4 f = *(const float4*)&g_F[((size_t)(b * NN + ig)) * OC + o4];
        float v0 = fmaf(rx, w0[0], f.x); v0 = fmaf(ry, w1[0], v0); v0 = fmaf(rz, w2[0], v0);
        float v1 = fmaf(rx, w0[1], f.y); v1 = fmaf(ry, w1[1], v1); v1 = fmaf(rz, w2[1], v1);
        float v2 = fmaf(rx, w0[2], f.z); v2 = fmaf(ry, w1[2], v2); v2 = fmaf(rz, w2[2], v2);
        float v3 = fmaf(rx, w0[3], f.w); v3 = fmaf(ry, w1[3], v3); v3 = fmaf(rz, w2[3], v3);
        m0 = fmaxf(m0, v0); m1 = fmaxf(m1, v1); m2 = fmaxf(m2, v2); m3 = fmaxf(m3, v3);
    }
    outf[((size_t)(b * OC + o4 + 0)) * SS + s] = m0;
    outf[((size_t)(b * OC + o4 + 1)) * SS + s] = m1;
    outf[((size_t)(b * OC + o4 + 2)) * SS + s] = m2;
    outf[((size_t)(b * OC + o4 + 3)) * SS + s] = m3;
}

// ---------------- K3: dense per-point feature GEMM  F[b][p][o] = fea·Wf ----------------
__global__ __launch_bounds__(256) void k_fgemm(const float* __restrict__ fea,
                                               const float* __restrict__ W) {
    __shared__ float As[32][128];   // [k][p]
    __shared__ float Bs[32][64];    // [k][o]
    int b  = blockIdx.z;
    int p0 = blockIdx.x * 128;
    int o0 = blockIdx.y * 64;
    int tx = threadIdx.x & 15;      // o tile (4 each)
    int ty = threadIdx.x >> 4;      // p tile (8 each)

    float acc[8][4];
#pragma unroll
    for (int i = 0; i < 8; i++)
#pragma unroll
        for (int j = 0; j < 4; j++) acc[i][j] = 0.f;

    for (int kk = 0; kk < CC; kk += 32) {
        __syncthreads();
        for (int i = threadIdx.x; i < 32 * 128; i += 256) {
            int cidx = i >> 7, p = i & 127;
            As[cidx][p] = fea[((size_t)(b * CC + kk + cidx)) * NN + p0 + p];
        }
        for (int i = threadIdx.x; i < 32 * 64; i += 256) {
            int cidx = i >> 6, o = i & 63;
            Bs[cidx][o] = W[(o0 + o) * 67 + kk + cidx];
        }
        __syncthreads();
#pragma unroll
        for (int k = 0; k < 32; k++) {
            float af[8], bf[4];
#pragma unroll
            for (int i = 0; i < 8; i++) af[i] = As[k][ty * 8 + i];
#pragma unroll
            for (int j = 0; j < 4; j++) bf[j] = Bs[k][tx * 4 + j];
#pragma unroll
            for (int i = 0; i < 8; i++)
#pragma unroll
                for (int j = 0; j < 4; j++)
                    acc[i][j] = fmaf(af[i], bf[j], acc[i][j]);
        }
    }
#pragma unroll
    for (int i = 0; i < 8; i++) {
        int p = p0 + ty * 8 + i;
        float4 v = make_float4(acc[i][0], acc[i][1], acc[i][2], acc[i][3]);
        *(float4*)&g_F[((size_t)(b * NN + p)) * OC + o0 + tx * 4] = v;
    }
}

// ---------------- launch: GEMM overlapped with FPS; group (fused final) last ----------------
extern "C" void kernel_launch(void* const* d_in, const int* in_sizes, int n_in,
                              void* d_out, int out_size) {
    const float* coor = (const float*)d_in[0];
    const float* fea  = (const float*)d_in[1];
    const float* W    = (const float*)d_in[2];
    float* outc = (float*)d_out;                 // (B,3,S)
    float* outf = outc + (size_t)BB * 3 * SS;    // (B,2C,S)

    static cudaStream_t s2 = nullptr;
    static cudaEvent_t evA = nullptr, evB = nullptr;
    if (s2 == nullptr) {
        cudaStreamCreateWithFlags(&s2, cudaStreamNonBlocking);
        cudaEventCreateWithFlags(&evA, cudaEventDisableTiming);
        cudaEventCreateWithFlags(&evB, cudaEventDisableTiming);
    }

    // fork: GEMM on side stream (independent of FPS); no cross-kernel spin waits.
    cudaEventRecord(evA, 0);
    cudaStreamWaitEvent(s2, evA, 0);
    k_fgemm<<<dim3(64, 2, BB), 256, 0, s2>>>(fea, W);
    cudaEventRecord(evB, s2);

    k_prep<<<dim3(32, BB), 256>>>(coor);
    k_fps <<<BB, 1024>>>(outc);

    // join: group reads g_F, so wait for GEMM (hidden under FPS)
    cudaStreamWaitEvent(0, evB, 0);
    k_group<<<dim3(64, BB), 512>>>(W, outf);
}

// round 13
// speedup vs baseline: 1.3749x; 1.2378x over previous
#include <cuda_runtime.h>

#define BB 16
#define NN 8192
#define SS 1024
#define GG 32
#define CC 64
#define OC 128
#define FULL 0xffffffffu
#define NSPLIT 4
#define SQ (SS / NSPLIT)

// ---------------- scratch (device globals; no runtime allocation) ----------------
__device__ float4 g_pts[BB * NN];                 // xyz + |p|^2
__device__ int    g_fps[BB * SS];                 // fps indices
__device__ int    g_gidx[BB * SS * GG];           // group indices (radius-replaced)
__device__ float  g_F[(size_t)BB * NN * OC];      // per-point feature @ Wf (64 MB)
__device__ float  g_dist[BB * NN];                // fps running min-dist (split resume)
__device__ float4 g_state[BB];                    // fps centroid + index (split resume)

// ---------------- packed f32x2 helpers (bit-identical .rn rounding) ----------------
__device__ __forceinline__ unsigned long long f2pack(float a, float b) {
    unsigned long long r;
    asm("mov.b64 %0, {%1, %2};" : "=l"(r) : "f"(a), "f"(b));
    return r;
}
__device__ __forceinline__ void f2unpack(unsigned long long v, float& a, float& b) {
    asm("mov.b64 {%0, %1}, %2;" : "=f"(a), "=f"(b) : "l"(v));
}
__device__ __forceinline__ unsigned long long fadd2(unsigned long long a, unsigned long long b) {
    unsigned long long r;
    asm("add.rn.f32x2 %0, %1, %2;" : "=l"(r) : "l"(a), "l"(b));
    return r;
}
__device__ __forceinline__ unsigned long long fmul2(unsigned long long a, unsigned long long b) {
    unsigned long long r;
    asm("mul.rn.f32x2 %0, %1, %2;" : "=l"(r) : "l"(a), "l"(b));
    return r;
}

// ---------------- K0: pack coords as float4 with squared norm ----------------
__global__ void k_prep(const float* __restrict__ coor) {
    int p = blockIdx.x * 256 + threadIdx.x;
    int b = blockIdx.y;
    if (p < NN) {
        float x = coor[((size_t)b * 3 + 0) * NN + p];
        float y = coor[((size_t)b * 3 + 1) * NN + p];
        float z = coor[((size_t)b * 3 + 2) * NN + p];
        g_pts[b * NN + p] = make_float4(x, y, z, x * x + y * y + z * z);
    }
}

// ---------------- K1: FPS part [s0, s1) — verified R2 step math, gmem-resumable ----------------
__global__ __launch_bounds__(1024) void k_fps_part(float* __restrict__ outc,
                                                   int s0, int s1) {
    __shared__ unsigned long long s_red[2][32];
    int b = blockIdx.x, tid = threadIdx.x, lane = tid & 31, wid = tid >> 5;
    const float4* pts = &g_pts[b * NN];

    unsigned long long px2[4], py2[4], pz2[4];
    float dist[8];
#pragma unroll
    for (int k = 0; k < 4; k++) {
        float4 a = pts[tid + ((2 * k) << 10)];
        float4 c = pts[tid + ((2 * k + 1) << 10)];
        px2[k] = f2pack(a.x, c.x);
        py2[k] = f2pack(a.y, c.y);
        pz2[k] = f2pack(a.z, c.z);
    }
    float cx, cy, cz; int cur;
    if (s0 == 0) {
#pragma unroll
        for (int k = 0; k < 8; k++) dist[k] = 1e10f;
        float4 c0 = pts[0];
        cx = c0.x; cy = c0.y; cz = c0.z; cur = 0;
    } else {
#pragma unroll
        for (int k = 0; k < 8; k++) dist[k] = g_dist[b * NN + tid + (k << 10)];
        float4 st = g_state[b];
        cx = st.x; cy = st.y; cz = st.z; cur = __float_as_int(st.w);
    }

    for (int s = s0; s < s1; s++) {
        if (tid == 0) {
            g_fps[b * SS + s] = cur;
            outc[((size_t)b * 3 + 0) * SS + s] = cx;
            outc[((size_t)b * 3 + 1) * SS + s] = cy;
            outc[((size_t)b * 3 + 2) * SS + s] = cz;
        }
        unsigned long long ncx2 = f2pack(-cx, -cx);
        unsigned long long ncy2 = f2pack(-cy, -cy);
        unsigned long long ncz2 = f2pack(-cz, -cz);
        float bm = -1.0f;
#pragma unroll
        for (int k = 0; k < 4; k++) {
            unsigned long long dx2 = fadd2(px2[k], ncx2);
            unsigned long long dy2 = fadd2(py2[k], ncy2);
            unsigned long long dz2 = fadd2(pz2[k], ncz2);
            unsigned long long sq = fadd2(fadd2(fmul2(dx2, dx2), fmul2(dy2, dy2)),
                                          fmul2(dz2, dz2));
            float d0, d1;
            f2unpack(sq, d0, d1);
            dist[2 * k]     = fminf(dist[2 * k], d0);
            dist[2 * k + 1] = fminf(dist[2 * k + 1], d1);
            bm = fmaxf(bm, dist[2 * k]);
            bm = fmaxf(bm, dist[2 * k + 1]);
        }
        int bk = 7;
#pragma unroll
        for (int k = 6; k >= 0; k--) bk = (dist[k] == bm) ? k : bk;

        unsigned vb = __float_as_uint(bm);
        unsigned m  = __reduce_max_sync(FULL, vb);
        unsigned rk = (vb == m) ? (unsigned)(NN - 1 - (tid + (bk << 10))) : 0u;
        unsigned m2 = __reduce_max_sync(FULL, rk);   // max(N-1-i) == min i
        if (lane == 0)
            s_red[s & 1][wid] = ((unsigned long long)m << 32) | m2;
        __syncthreads();
        unsigned long long v = s_red[s & 1][lane];
        unsigned hi = (unsigned)(v >> 32);
        unsigned M  = __reduce_max_sync(FULL, hi);
        unsigned lo = (hi == M) ? (unsigned)v : 0u;
        unsigned M2 = __reduce_max_sync(FULL, lo);
        int nf = NN - 1 - (int)M2;
        float4 cc = pts[nf];
        cx = cc.x; cy = cc.y; cz = cc.z; cur = nf;
    }

    // persist resume state (exact bits)
#pragma unroll
    for (int k = 0; k < 8; k++) g_dist[b * NN + tid + (k << 10)] = dist[k];
    if (tid == 0) g_state[b] = make_float4(cx, cy, cz, __int_as_float(cur));
}

// ---------------- K2: radius-filtered replace-max top-32 (de-fused; writes g_gidx) ----------------
__global__ __launch_bounds__(512) void k_group(int s0) {
    int b    = blockIdx.y;
    int warp = threadIdx.x >> 5, lane = threadIdx.x & 31;
    int s    = s0 + blockIdx.x * 16 + warp;
    const float4* pts = &g_pts[b * NN];

    float4 c = pts[g_fps[b * SS + s]];
    float cx = c.x, cy = c.y, cz = c.z, cw = c.w;

    const unsigned long long UMX    = 0xffffffffffffffffull;
    const unsigned long long RADCAP = 0xBF800001ull << 32;   // admit d <= 1.0

    unsigned long long kept = UMX;         // sentinel = empty slot
    unsigned long long adm  = RADCAP;      // admission = min(worst kept, RADCAP)
    unsigned adm_hi = 0xBF800001u;
    int maxLane = 0;

    for (int base = 0; base < NN; base += 32) {
        float4 q = pts[base + lane];
        float dot = fmaf(cx, q.x, fmaf(cy, q.y, cz * q.z));
        float d   = fmaf(-2.f, dot, cw + q.w);
        unsigned bits = __float_as_uint(d);
        unsigned uu = bits ^ (unsigned)(((int)bits >> 31) | (int)0x80000000);
        unsigned mask = __ballot_sync(FULL, uu < adm_hi);
        if (mask) {
            unsigned long long key = ((unsigned long long)uu << 32) | (unsigned)(base + lane);
            do {
                int src = __ffs(mask) - 1; mask &= mask - 1;
                unsigned long long kk = __shfl_sync(FULL, key, src);
                if (kk < adm) {
                    if (lane == maxLane) kept = kk;
                    unsigned hi = (unsigned)(kept >> 32);
                    unsigned M  = __reduce_max_sync(FULL, hi);
                    unsigned lo = (hi == M) ? (unsigned)kept : 0u;
                    unsigned M2 = __reduce_max_sync(FULL, lo);
                    unsigned long long true_key = ((unsigned long long)M << 32) | M2;
                    maxLane = __ffs(__ballot_sync(FULL, kept == true_key)) - 1;
                    adm = (true_key < RADCAP) ? true_key : RADCAP;
                    adm_hi = (unsigned)(adm >> 32);
                }
            } while (mask);
        }
    }

    // nearest (min kept) fills replaced/empty slots
    unsigned khi = (unsigned)(kept >> 32);
    unsigned Mn  = __reduce_min_sync(FULL, khi);
    unsigned lon = (khi == Mn) ? (unsigned)kept : 0xffffffffu;
    unsigned M2n = __reduce_min_sync(FULL, lon);
    int nidx  = (int)M2n;
    int myidx = (int)(unsigned)kept;
    int outi = (khi > 0xBF800000u) ? nidx : myidx;
    g_gidx[(b * SS + s) * GG + lane] = outi;
}

// ---------------- K4: gather + coord term + ReLU + group max (verified R2 version) ----------------
__global__ __launch_bounds__(128) void k_final(const float* __restrict__ W,
                                               const float* __restrict__ outc,
                                               float* __restrict__ outf, int s0) {
    __shared__ int   s_idx[GG];
    __shared__ float s_rc[3][GG];
    int b = blockIdx.y, s = s0 + blockIdx.x;
    int tid = threadIdx.x;
    if (tid < GG) {
        int i = g_gidx[(b * SS + s) * GG + tid];
        s_idx[tid] = i;
        float4 p = g_pts[b * NN + i];
        s_rc[0][tid] = p.x - outc[((size_t)b * 3 + 0) * SS + s];
        s_rc[1][tid] = p.y - outc[((size_t)b * 3 + 1) * SS + s];
        s_rc[2][tid] = p.z - outc[((size_t)b * 3 + 2) * SS + s];
    }
    __syncthreads();
    int o = tid;
    float w0 = W[o * 67 + 64], w1 = W[o * 67 + 65], w2 = W[o * 67 + 66];
    float m = 0.f;   // relu(v) >= 0
#pragma unroll 8
    for (int g = 0; g < GG; g++) {
        float v = g_F[((size_t)(b * NN + s_idx[g])) * OC + o];
        v = fmaf(s_rc[0][g], w0, v);
        v = fmaf(s_rc[1][g], w1, v);
        v = fmaf(s_rc[2][g], w2, v);
        m = fmaxf(m, v);
    }
    outf[((size_t)(b * OC + o)) * SS + s] = m;
}

// ---------------- K3: dense per-point feature GEMM  F[b][p][o] = fea·Wf ----------------
__global__ __launch_bounds__(256) void k_fgemm(const float* __restrict__ fea,
                                               const float* __restrict__ W) {
    __shared__ float As[32][128];
    __shared__ float Bs[32][64];
    int b  = blockIdx.z;
    int p0 = blockIdx.x * 128;
    int o0 = blockIdx.y * 64;
    int tx = threadIdx.x & 15;
    int ty = threadIdx.x >> 4;

    float acc[8][4];
#pragma unroll
    for (int i = 0; i < 8; i++)
#pragma unroll
        for (int j = 0; j < 4; j++) acc[i][j] = 0.f;

    for (int kk = 0; kk < CC; kk += 32) {
        __syncthreads();
        for (int i = threadIdx.x; i < 32 * 128; i += 256) {
            int cidx = i >> 7, p = i & 127;
            As[cidx][p] = fea[((size_t)(b * CC + kk + cidx)) * NN + p0 + p];
        }
        for (int i = threadIdx.x; i < 32 * 64; i += 256) {
            int cidx = i >> 6, o = i & 63;
            Bs[cidx][o] = W[(o0 + o) * 67 + kk + cidx];
        }
        __syncthreads();
#pragma unroll
        for (int k = 0; k < 32; k++) {
            float af[8], bf[4];
#pragma unroll
            for (int i = 0; i < 8; i++) af[i] = As[k][ty * 8 + i];
#pragma unroll
            for (int j = 0; j < 4; j++) bf[j] = Bs[k][tx * 4 + j];
#pragma unroll
            for (int i = 0; i < 8; i++)
#pragma unroll
                for (int j = 0; j < 4; j++)
                    acc[i][j] = fmaf(af[i], bf[j], acc[i][j]);
        }
    }
#pragma unroll
    for (int i = 0; i < 8; i++) {
        int p = p0 + ty * 8 + i;
        float4 v = make_float4(acc[i][0], acc[i][1], acc[i][2], acc[i][3]);
        *(float4*)&g_F[((size_t)(b * NN + p)) * OC + o0 + tx * 4] = v;
    }
}

// ---------------- launch: 4-way FPS split pipelined with group/final quarters ----------------
extern "C" void kernel_launch(void* const* d_in, const int* in_sizes, int n_in,
                              void* d_out, int out_size) {
    const float* coor = (const float*)d_in[0];
    const float* fea  = (const float*)d_in[1];
    const float* W    = (const float*)d_in[2];
    float* outc = (float*)d_out;                 // (B,3,S)
    float* outf = outc + (size_t)BB * 3 * SS;    // (B,2C,S)

    static cudaStream_t s2 = nullptr;
    static cudaEvent_t evP = nullptr, evF[NSPLIT - 1] = {}, evS2 = nullptr;
    if (s2 == nullptr) {
        cudaStreamCreateWithFlags(&s2, cudaStreamNonBlocking);
        cudaEventCreateWithFlags(&evP, cudaEventDisableTiming);
        for (int i = 0; i < NSPLIT - 1; i++)
            cudaEventCreateWithFlags(&evF[i], cudaEventDisableTiming);
        cudaEventCreateWithFlags(&evS2, cudaEventDisableTiming);
    }

    // main: prep, then fps parts back-to-back
    k_prep<<<dim3(32, BB), 256>>>(coor);
    cudaEventRecord(evP, 0);

    // side: gemm first (only needs fea/W; overlaps fps1-2)
    cudaStreamWaitEvent(s2, evP, 0);
    k_fgemm<<<dim3(64, 2, BB), 256, 0, s2>>>(fea, W);

    for (int q = 0; q < NSPLIT; q++) {
        k_fps_part<<<BB, 1024>>>(outc, q * SQ, (q + 1) * SQ);
        if (q < NSPLIT - 1) cudaEventRecord(evF[q], 0);
    }
    // side: group+final quarters as fps parts complete (event deps only — no spins)
    for (int q = 0; q < NSPLIT - 1; q++) {
        cudaStreamWaitEvent(s2, evF[q], 0);
        k_group<<<dim3(SQ / 16, BB), 512, 0, s2>>>(q * SQ);
        k_final<<<dim3(SQ, BB), 128, 0, s2>>>(W, outc, outf, q * SQ);
    }
    cudaEventRecord(evS2, s2);

    // main: last quarter after fps4 (and after side stream, which implies gemm done)
    cudaStreamWaitEvent(0, evS2, 0);
    k_group<<<dim3(SQ / 16, BB), 512>>>((NSPLIT - 1) * SQ);
    k_final<<<dim3(SQ, BB), 128>>>(W, outc, outf, (NSPLIT - 1) * SQ);
}

// round 15
// speedup vs baseline: 1.4042x; 1.0213x over previous
#include <cuda_runtime.h>

#define BB 16
#define NN 8192
#define SS 1024
#define GG 32
#define CC 64
#define OC 128
#define FULL 0xffffffffu
#define NSPLIT 8
#define SQ (SS / NSPLIT)

// ---------------- scratch (device globals; no runtime allocation) ----------------
__device__ float4 g_pts[BB * NN];                 // xyz + |p|^2
__device__ int    g_fps[BB * SS];                 // fps indices
__device__ int    g_gidx[BB * SS * GG];           // group indices (radius-replaced)
__device__ float  g_F[(size_t)BB * NN * OC];      // per-point feature @ Wf (64 MB)
__device__ float  g_dist[BB * NN];                // fps running min-dist (split resume)
__device__ float4 g_state[BB];                    // fps centroid + index (split resume)

// ---------------- packed f32x2 helpers ----------------
__device__ __forceinline__ unsigned long long f2pack(float a, float b) {
    unsigned long long r;
    asm("mov.b64 %0, {%1, %2};" : "=l"(r) : "f"(a), "f"(b));
    return r;
}
__device__ __forceinline__ void f2unpack(unsigned long long v, float& a, float& b) {
    asm("mov.b64 {%0, %1}, %2;" : "=f"(a), "=f"(b) : "l"(v));
}
__device__ __forceinline__ unsigned long long fadd2(unsigned long long a, unsigned long long b) {
    unsigned long long r;
    asm("add.rn.f32x2 %0, %1, %2;" : "=l"(r) : "l"(a), "l"(b));
    return r;
}
__device__ __forceinline__ unsigned long long fmul2(unsigned long long a, unsigned long long b) {
    unsigned long long r;
    asm("mul.rn.f32x2 %0, %1, %2;" : "=l"(r) : "l"(a), "l"(b));
    return r;
}
__device__ __forceinline__ unsigned long long ffma2(unsigned long long a, unsigned long long b,
                                                    unsigned long long c) {
    unsigned long long r;
    asm("fma.rn.f32x2 %0, %1, %2, %3;" : "=l"(r) : "l"(a), "l"(b), "l"(c));
    return r;
}

// ---------------- K0: pack coords as float4 with squared norm ----------------
__global__ void k_prep(const float* __restrict__ coor) {
    int p = blockIdx.x * 256 + threadIdx.x;
    int b = blockIdx.y;
    if (p < NN) {
        float x = coor[((size_t)b * 3 + 0) * NN + p];
        float y = coor[((size_t)b * 3 + 1) * NN + p];
        float z = coor[((size_t)b * 3 + 2) * NN + p];
        g_pts[b * NN + p] = make_float4(x, y, z, x * x + y * y + z * z);
    }
}

// ---------------- K1: FPS part [s0, s1) — fma2 inner loop, gmem-resumable ----------------
__global__ __launch_bounds__(1024) void k_fps_part(float* __restrict__ outc,
                                                   int s0, int s1) {
    __shared__ unsigned long long s_red[2][32];
    int b = blockIdx.x, tid = threadIdx.x, lane = tid & 31, wid = tid >> 5;
    const float4* pts = &g_pts[b * NN];

    unsigned long long px2[4], py2[4], pz2[4];
    float dist[8];
#pragma unroll
    for (int k = 0; k < 4; k++) {
        float4 a = pts[tid + ((2 * k) << 10)];
        float4 c = pts[tid + ((2 * k + 1) << 10)];
        px2[k] = f2pack(a.x, c.x);
        py2[k] = f2pack(a.y, c.y);
        pz2[k] = f2pack(a.z, c.z);
    }
    float cx, cy, cz; int cur;
    if (s0 == 0) {
#pragma unroll
        for (int k = 0; k < 8; k++) dist[k] = 1e10f;
        float4 c0 = pts[0];
        cx = c0.x; cy = c0.y; cz = c0.z; cur = 0;
    } else {
#pragma unroll
        for (int k = 0; k < 8; k++) dist[k] = g_dist[b * NN + tid + (k << 10)];
        float4 st = g_state[b];
        cx = st.x; cy = st.y; cz = st.z; cur = __float_as_int(st.w);
    }

    for (int s = s0; s < s1; s++) {
        if (tid == 0) {
            g_fps[b * SS + s] = cur;
            outc[((size_t)b * 3 + 0) * SS + s] = cx;
            outc[((size_t)b * 3 + 1) * SS + s] = cy;
            outc[((size_t)b * 3 + 2) * SS + s] = cz;
        }
        unsigned long long ncx2 = f2pack(-cx, -cx);
        unsigned long long ncy2 = f2pack(-cy, -cy);
        unsigned long long ncz2 = f2pack(-cz, -cz);
        float bm = -1.0f;
#pragma unroll
        for (int k = 0; k < 4; k++) {
            unsigned long long dx2 = fadd2(px2[k], ncx2);
            unsigned long long dy2 = fadd2(py2[k], ncy2);
            unsigned long long dz2 = fadd2(pz2[k], ncz2);
            // dz*dz + (dy*dy + dx*dx) via fma chain: <=1 ulp vs reference association
            unsigned long long sq = ffma2(dz2, dz2, ffma2(dy2, dy2, fmul2(dx2, dx2)));
            float d0, d1;
            f2unpack(sq, d0, d1);
            dist[2 * k]     = fminf(dist[2 * k], d0);
            dist[2 * k + 1] = fminf(dist[2 * k + 1], d1);
            bm = fmaxf(bm, dist[2 * k]);
            bm = fmaxf(bm, dist[2 * k + 1]);
        }
        int bk = 7;
#pragma unroll
        for (int k = 6; k >= 0; k--) bk = (dist[k] == bm) ? k : bk;

        unsigned vb = __float_as_uint(bm);
        unsigned m  = __reduce_max_sync(FULL, vb);
        unsigned rk = (vb == m) ? (unsigned)(NN - 1 - (tid + (bk << 10))) : 0u;
        unsigned m2 = __reduce_max_sync(FULL, rk);   // max(N-1-i) == min i
        if (lane == 0)
            s_red[s & 1][wid] = ((unsigned long long)m << 32) | m2;
        __syncthreads();
        unsigned long long v = s_red[s & 1][lane];
        unsigned hi = (unsigned)(v >> 32);
        unsigned M  = __reduce_max_sync(FULL, hi);
        unsigned lo = (hi == M) ? (unsigned)v : 0u;
        unsigned M2 = __reduce_max_sync(FULL, lo);
        int nf = NN - 1 - (int)M2;
        float4 cc = pts[nf];
        cx = cc.x; cy = cc.y; cz = cc.z; cur = nf;
    }

    // persist resume state (exact bits)
#pragma unroll
    for (int k = 0; k < 8; k++) g_dist[b * NN + tid + (k << 10)] = dist[k];
    if (tid == 0) g_state[b] = make_float4(cx, cy, cz, __int_as_float(cur));
}

// ---------------- K2: radius-filtered replace-max top-32 (writes g_gidx) ----------------
__global__ __launch_bounds__(512) void k_group(int s0) {
    int b    = blockIdx.y;
    int warp = threadIdx.x >> 5, lane = threadIdx.x & 31;
    int s    = s0 + blockIdx.x * 16 + warp;
    const float4* pts = &g_pts[b * NN];

    float4 c = pts[g_fps[b * SS + s]];
    float cx = c.x, cy = c.y, cz = c.z, cw = c.w;

    const unsigned long long UMX    = 0xffffffffffffffffull;
    const unsigned long long RADCAP = 0xBF800001ull << 32;   // admit d <= 1.0

    unsigned long long kept = UMX;         // sentinel = empty slot
    unsigned long long adm  = RADCAP;      // admission = min(worst kept, RADCAP)
    unsigned adm_hi = 0xBF800001u;
    int maxLane = 0;

    for (int base = 0; base < NN; base += 32) {
        float4 q = pts[base + lane];
        float dot = fmaf(cx, q.x, fmaf(cy, q.y, cz * q.z));
        float d   = fmaf(-2.f, dot, cw + q.w);
        unsigned bits = __float_as_uint(d);
        unsigned uu = bits ^ (unsigned)(((int)bits >> 31) | (int)0x80000000);
        unsigned mask = __ballot_sync(FULL, uu < adm_hi);
        if (mask) {
            unsigned long long key = ((unsigned long long)uu << 32) | (unsigned)(base + lane);
            do {
                int src = __ffs(mask) - 1; mask &= mask - 1;
                unsigned long long kk = __shfl_sync(FULL, key, src);
                if (kk < adm) {
                    if (lane == maxLane) kept = kk;
                    unsigned hi = (unsigned)(kept >> 32);
                    unsigned M  = __reduce_max_sync(FULL, hi);
                    unsigned lo = (hi == M) ? (unsigned)kept : 0u;
                    unsigned M2 = __reduce_max_sync(FULL, lo);
                    unsigned long long true_key = ((unsigned long long)M << 32) | M2;
                    maxLane = __ffs(__ballot_sync(FULL, kept == true_key)) - 1;
                    adm = (true_key < RADCAP) ? true_key : RADCAP;
                    adm_hi = (unsigned)(adm >> 32);
                }
            } while (mask);
        }
    }

    // nearest (min kept) fills replaced/empty slots
    unsigned khi = (unsigned)(kept >> 32);
    unsigned Mn  = __reduce_min_sync(FULL, khi);
    unsigned lon = (khi == Mn) ? (unsigned)kept : 0xffffffffu;
    unsigned M2n = __reduce_min_sync(FULL, lon);
    int nidx  = (int)M2n;
    int myidx = (int)(unsigned)kept;
    int outi = (khi > 0xBF800000u) ? nidx : myidx;
    g_gidx[(b * SS + s) * GG + lane] = outi;
}

// ---------------- K4: gather + coord term + ReLU + group max ----------------
__global__ __launch_bounds__(128) void k_final(const float* __restrict__ W,
                                               const float* __restrict__ outc,
                                               float* __restrict__ outf, int s0) {
    __shared__ int   s_idx[GG];
    __shared__ float s_rc[3][GG];
    int b = blockIdx.y, s = s0 + blockIdx.x;
    int tid = threadIdx.x;
    if (tid < GG) {
        int i = g_gidx[(b * SS + s) * GG + tid];
        s_idx[tid] = i;
        float4 p = g_pts[b * NN + i];
        s_rc[0][tid] = p.x - outc[((size_t)b * 3 + 0) * SS + s];
        s_rc[1][tid] = p.y - outc[((size_t)b * 3 + 1) * SS + s];
        s_rc[2][tid] = p.z - outc[((size_t)b * 3 + 2) * SS + s];
    }
    __syncthreads();
    int o = tid;
    float w0 = W[o * 67 + 64], w1 = W[o * 67 + 65], w2 = W[o * 67 + 66];
    float m = 0.f;   // relu(v) >= 0
#pragma unroll 8
    for (int g = 0; g < GG; g++) {
        float v = g_F[((size_t)(b * NN + s_idx[g])) * OC + o];
        v = fmaf(s_rc[0][g], w0, v);
        v = fmaf(s_rc[1][g], w1, v);
        v = fmaf(s_rc[2][g], w2, v);
        m = fmaxf(m, v);
    }
    outf[((size_t)(b * OC + o)) * SS + s] = m;
}

// ---------------- K3: dense per-point feature GEMM  F[b][p][o] = fea·Wf ----------------
__global__ __launch_bounds__(256) void k_fgemm(const float* __restrict__ fea,
                                               const float* __restrict__ W) {
    __shared__ float As[32][128];
    __shared__ float Bs[32][64];
    int b  = blockIdx.z;
    int p0 = blockIdx.x * 128;
    int o0 = blockIdx.y * 64;
    int tx = threadIdx.x & 15;
    int ty = threadIdx.x >> 4;

    float acc[8][4];
#pragma unroll
    for (int i = 0; i < 8; i++)
#pragma unroll
        for (int j = 0; j < 4; j++) acc[i][j] = 0.f;

    for (int kk = 0; kk < CC; kk += 32) {
        __syncthreads();
        for (int i = threadIdx.x; i < 32 * 128; i += 256) {
            int cidx = i >> 7, p = i & 127;
            As[cidx][p] = fea[((size_t)(b * CC + kk + cidx)) * NN + p0 + p];
        }
        for (int i = threadIdx.x; i < 32 * 64; i += 256) {
            int cidx = i >> 6, o = i & 63;
            Bs[cidx][o] = W[(o0 + o) * 67 + kk + cidx];
        }
        __syncthreads();
#pragma unroll
        for (int k = 0; k < 32; k++) {
            float af[8], bf[4];
#pragma unroll
            for (int i = 0; i < 8; i++) af[i] = As[k][ty * 8 + i];
#pragma unroll
            for (int j = 0; j < 4; j++) bf[j] = Bs[k][tx * 4 + j];
#pragma unroll
            for (int i = 0; i < 8; i++)
#pragma unroll
                for (int j = 0; j < 4; j++)
                    acc[i][j] = fmaf(af[i], bf[j], acc[i][j]);
        }
    }
#pragma unroll
    for (int i = 0; i < 8; i++) {
        int p = p0 + ty * 8 + i;
        float4 v = make_float4(acc[i][0], acc[i][1], acc[i][2], acc[i][3]);
        *(float4*)&g_F[((size_t)(b * NN + p)) * OC + o0 + tx * 4] = v;
    }
}

// ---------------- launch: 8-way FPS split pipelined with group/final slices ----------------
extern "C" void kernel_launch(void* const* d_in, const int* in_sizes, int n_in,
                              void* d_out, int out_size) {
    const float* coor = (const float*)d_in[0];
    const float* fea  = (const float*)d_in[1];
    const float* W    = (const float*)d_in[2];
    float* outc = (float*)d_out;                 // (B,3,S)
    float* outf = outc + (size_t)BB * 3 * SS;    // (B,2C,S)

    static cudaStream_t s2 = nullptr;
    static cudaEvent_t evP = nullptr, evF[NSPLIT - 1] = {}, evS2 = nullptr;
    if (s2 == nullptr) {
        cudaStreamCreateWithFlags(&s2, cudaStreamNonBlocking);
        cudaEventCreateWithFlags(&evP, cudaEventDisableTiming);
        for (int i = 0; i < NSPLIT - 1; i++)
            cudaEventCreateWithFlags(&evF[i], cudaEventDisableTiming);
        cudaEventCreateWithFlags(&evS2, cudaEventDisableTiming);
    }

    // main: prep, then fps parts back-to-back
    k_prep<<<dim3(32, BB), 256>>>(coor);
    cudaEventRecord(evP, 0);

    // side: gemm first (only needs fea/W; overlaps early fps parts)
    cudaStreamWaitEvent(s2, evP, 0);
    k_fgemm<<<dim3(64, 2, BB), 256, 0, s2>>>(fea, W);

    for (int q = 0; q < NSPLIT; q++) {
        k_fps_part<<<BB, 1024>>>(outc, q * SQ, (q + 1) * SQ);
        if (q < NSPLIT - 1) cudaEventRecord(evF[q], 0);
    }
    // side: group+final slices as fps parts complete (event deps only — no spins)
    for (int q = 0; q < NSPLIT - 1; q++) {
        cudaStreamWaitEvent(s2, evF[q], 0);
        k_group<<<dim3(SQ / 16, BB), 512, 0, s2>>>(q * SQ);
        k_final<<<dim3(SQ, BB), 128, 0, s2>>>(W, outc, outf, q * SQ);
    }
    cudaEventRecord(evS2, s2);

    // main: last slice after fps8 (and after side stream => gemm done)
    cudaStreamWaitEvent(0, evS2, 0);
    k_group<<<dim3(SQ / 16, BB), 512>>>((NSPLIT - 1) * SQ);
    k_final<<<dim3(SQ, BB), 128>>>(W, outc, outf, (NSPLIT - 1) * SQ);
}